// round 1
// baseline (speedup 1.0000x reference)
#include <cuda_runtime.h>
#include <cuda_bf16.h>
#include <math.h>

// Problem constants (fixed by setup_inputs)
#define DIMC   1024
#define NHC    16
#define HDC    64
#define FQ     16          // frames
#define SQ     1472        // tokens per frame
#define TROWS  (FQ * SQ)   // 23552 total rows
#define WINDOW 8

// ---------------- scratch (device globals; no allocation allowed) ----------
__device__ float g_q[(size_t)TROWS * DIMC];
__device__ float g_k[(size_t)TROWS * DIMC];
__device__ float g_v[(size_t)TROWS * DIMC];
__device__ float g_o[(size_t)TROWS * DIMC];

// ---------------- SGEMM: C[M,1024] = A[M,1024] @ W[1024,1024]^T + bias -----
// Both A and W are row-major with K contiguous (NT gemm).
// Block tile 128x128, K-tile 16, 256 threads, 8x8 per-thread microtile.
#define BM 128
#define BN 128
#define BK 16

__global__ __launch_bounds__(256, 2)
void sgemm_bias_kernel(const float* __restrict__ A,
                       const float* __restrict__ W,
                       const float* __restrict__ bias,
                       float* __restrict__ C)
{
    __shared__ float As[BK][BM + 4];
    __shared__ float Bs[BK][BN + 4];

    const int K  = DIMC;
    const int bm = blockIdx.y * BM;
    const int bn = blockIdx.x * BN;
    const int tid = threadIdx.x;
    const int tx = tid & 15;   // 0..15 -> n
    const int ty = tid >> 4;   // 0..15 -> m

    const int lr = tid >> 2;   // 0..63 (row within tile, +64 on 2nd iter)
    const int lc = tid & 3;    // 0..3  (float4 column in K-tile)

    float acc[8][8];
#pragma unroll
    for (int i = 0; i < 8; ++i)
#pragma unroll
        for (int j = 0; j < 8; ++j) acc[i][j] = 0.f;

    for (int k0 = 0; k0 < K; k0 += BK) {
#pragma unroll
        for (int it = 0; it < 2; ++it) {
            int r = lr + it * 64;
            float4 a = *(const float4*)&A[(size_t)(bm + r) * K + k0 + lc * 4];
            As[lc * 4 + 0][r] = a.x;
            As[lc * 4 + 1][r] = a.y;
            As[lc * 4 + 2][r] = a.z;
            As[lc * 4 + 3][r] = a.w;
            float4 b = *(const float4*)&W[(size_t)(bn + r) * K + k0 + lc * 4];
            Bs[lc * 4 + 0][r] = b.x;
            Bs[lc * 4 + 1][r] = b.y;
            Bs[lc * 4 + 2][r] = b.z;
            Bs[lc * 4 + 3][r] = b.w;
        }
        __syncthreads();

#pragma unroll
        for (int k = 0; k < BK; ++k) {
            float a[8], b[8];
            *(float4*)&a[0] = *(const float4*)&As[k][ty * 8];
            *(float4*)&a[4] = *(const float4*)&As[k][ty * 8 + 4];
            *(float4*)&b[0] = *(const float4*)&Bs[k][tx * 8];
            *(float4*)&b[4] = *(const float4*)&Bs[k][tx * 8 + 4];
#pragma unroll
            for (int i = 0; i < 8; ++i)
#pragma unroll
                for (int j = 0; j < 8; ++j)
                    acc[i][j] += a[i] * b[j];
        }
        __syncthreads();
    }

    // epilogue: add bias, store
#pragma unroll
    for (int i = 0; i < 8; ++i) {
        const int row = bm + ty * 8 + i;
        float* Crow = &C[(size_t)row * DIMC + bn + tx * 8];
#pragma unroll
        for (int j4 = 0; j4 < 2; ++j4) {
            const int col = bn + tx * 8 + j4 * 4;
            float4 r;
            r.x = acc[i][j4 * 4 + 0] + bias[col + 0];
            r.y = acc[i][j4 * 4 + 1] + bias[col + 1];
            r.z = acc[i][j4 * 4 + 2] + bias[col + 2];
            r.w = acc[i][j4 * 4 + 3] + bias[col + 3];
            *(float4*)&Crow[j4 * 4] = r;
        }
    }
}

// ---------------- fused RMSNorm + RoPE (in place, one block per row) -------
__global__ __launch_bounds__(256)
void rmsnorm_rope_kernel(float* __restrict__ hk,
                         const float* __restrict__ w,
                         const float* __restrict__ fcos,
                         const float* __restrict__ fsin)
{
    const int t   = blockIdx.x;           // row == position index (frame*SQ+si)
    const int tid = threadIdx.x;          // 256 threads, 4 elements each
    const int col = tid * 4;

    float4 v = *(float4*)&hk[(size_t)t * DIMC + col];
    float local = v.x * v.x + v.y * v.y + v.z * v.z + v.w * v.w;

#pragma unroll
    for (int o = 16; o > 0; o >>= 1)
        local += __shfl_xor_sync(0xffffffffu, local, o);

    __shared__ float red[8];
    if ((tid & 31) == 0) red[tid >> 5] = local;
    __syncthreads();

    float tot = red[0] + red[1] + red[2] + red[3] +
                red[4] + red[5] + red[6] + red[7];
    const float scale = rsqrtf(tot * (1.0f / 1024.0f) + 1e-6f);

    float h0 = v.x * scale * w[col + 0];
    float h1 = v.y * scale * w[col + 1];
    float h2 = v.z * scale * w[col + 2];
    float h3 = v.w * scale * w[col + 3];

    // rope: pairs (col,col+1) and (col+2,col+3); per-head pair index
    const int dd0 = ((col & 63) >> 1);    // 0..30 (even)
    const int dd1 = dd0 + 1;
    const float c0 = fcos[(size_t)t * 32 + dd0];
    const float s0 = fsin[(size_t)t * 32 + dd0];
    const float c1 = fcos[(size_t)t * 32 + dd1];
    const float s1 = fsin[(size_t)t * 32 + dd1];

    float4 outv;
    outv.x = h0 * c0 - h1 * s0;
    outv.y = h0 * s0 + h1 * c0;
    outv.z = h2 * c1 - h3 * s1;
    outv.w = h2 * s1 + h3 * c1;
    *(float4*)&hk[(size_t)t * DIMC + col] = outv;
}

// ---------------- windowed frame attention ---------------------------------
// One block per (si, head). 16 frames x 64 dims per head. Mask: j<=i, i-j<8.
__global__ __launch_bounds__(128)
void attn_kernel(const float* __restrict__ q,
                 const float* __restrict__ k,
                 const float* __restrict__ v,
                 float* __restrict__ o)
{
    const int si  = blockIdx.x;   // 0..1471
    const int h   = blockIdx.y;   // 0..15
    const int tid = threadIdx.x;  // 128

    __shared__ float sq[16][64];
    __shared__ float sk[16][64];
    __shared__ float sv[16][64];
    __shared__ float sS[16][17];

    // load q/k/v tiles for this (si,h): rows t = frame*SQ + si, cols h*64..h*64+63
#pragma unroll
    for (int e = tid; e < 256; e += 128) {
        const int frame = e >> 4;
        const int d4    = (e & 15) * 4;
        const size_t base = ((size_t)(frame * SQ + si)) * DIMC + h * HDC + d4;
        *(float4*)&sq[frame][d4] = *(const float4*)&q[base];
        *(float4*)&sk[frame][d4] = *(const float4*)&k[base];
        *(float4*)&sv[frame][d4] = *(const float4*)&v[base];
    }
    __syncthreads();

    // scores (masked)
#pragma unroll
    for (int p = tid; p < 256; p += 128) {
        const int i = p >> 4;
        const int j = p & 15;
        float s;
        if (j <= i && (i - j) < WINDOW) {
            float accd = 0.f;
#pragma unroll
            for (int d = 0; d < 64; ++d) accd += sq[i][d] * sk[j][d];
            s = accd * 0.125f;           // 1/sqrt(64)
        } else {
            s = -1e30f;
        }
        sS[i][j] = s;
    }
    __syncthreads();

    // softmax per row (16 rows)
    if (tid < 16) {
        const int i = tid;
        float m = -1e30f;
#pragma unroll
        for (int j = 0; j < 16; ++j) m = fmaxf(m, sS[i][j]);
        float e[16];
        float sum = 0.f;
#pragma unroll
        for (int j = 0; j < 16; ++j) { e[j] = expf(sS[i][j] - m); sum += e[j]; }
        const float inv = 1.f / sum;
#pragma unroll
        for (int j = 0; j < 16; ++j) sS[i][j] = e[j] * inv;
    }
    __syncthreads();

    // O = attn @ V, written back in x-layout: row = frame*SQ + si
#pragma unroll
    for (int e2 = tid; e2 < 1024; e2 += 128) {
        const int i = e2 >> 6;
        const int d = e2 & 63;
        float accd = 0.f;
#pragma unroll
        for (int j = 0; j < 16; ++j) accd += sS[i][j] * sv[j][d];
        o[((size_t)(i * SQ + si)) * DIMC + h * HDC + d] = accd;
    }
}

// ---------------- launch ----------------------------------------------------
extern "C" void kernel_launch(void* const* d_in, const int* in_sizes, int n_in,
                              void* d_out, int out_size)
{
    const float* x   = (const float*)d_in[0];
    const float* fc  = (const float*)d_in[1];
    const float* fs  = (const float*)d_in[2];
    const float* q_w = (const float*)d_in[3];
    const float* q_b = (const float*)d_in[4];
    const float* k_w = (const float*)d_in[5];
    const float* k_b = (const float*)d_in[6];
    const float* v_w = (const float*)d_in[7];
    const float* v_b = (const float*)d_in[8];
    const float* o_w = (const float*)d_in[9];
    const float* o_b = (const float*)d_in[10];
    const float* nqw = (const float*)d_in[11];
    const float* nkw = (const float*)d_in[12];
    float* out = (float*)d_out;

    float *gq, *gk, *gv, *go;
    cudaGetSymbolAddress((void**)&gq, g_q);
    cudaGetSymbolAddress((void**)&gk, g_k);
    cudaGetSymbolAddress((void**)&gv, g_v);
    cudaGetSymbolAddress((void**)&go, g_o);

    const dim3 gemm_grid(DIMC / BN, TROWS / BM);   // (8, 184)

    // QKV projections
    sgemm_bias_kernel<<<gemm_grid, 256>>>(x, q_w, q_b, gq);
    sgemm_bias_kernel<<<gemm_grid, 256>>>(x, k_w, k_b, gk);
    sgemm_bias_kernel<<<gemm_grid, 256>>>(x, v_w, v_b, gv);

    // RMSNorm + RoPE (in place) on q and k
    rmsnorm_rope_kernel<<<TROWS, 256>>>(gq, nqw, fc, fs);
    rmsnorm_rope_kernel<<<TROWS, 256>>>(gk, nkw, fc, fs);

    // windowed frame attention
    attn_kernel<<<dim3(SQ, NHC), 128>>>(gq, gk, gv, go);

    // output projection
    sgemm_bias_kernel<<<gemm_grid, 256>>>(go, o_w, o_b, out);
}

// round 3
// speedup vs baseline: 2.7512x; 2.7512x over previous
#include <cuda_runtime.h>
#include <cuda_bf16.h>
#include <cstdint>
#include <math.h>

// Problem constants (fixed by setup_inputs)
#define DIMC   1024
#define NHC    16
#define HDC    64
#define FQ     16          // frames
#define SQ     1472        // tokens per frame
#define TROWS  (FQ * SQ)   // 23552 total rows
#define WINDOW 8

// ---------------- scratch (device globals; no allocation allowed) ----------
__device__ float g_q[(size_t)TROWS * DIMC];
__device__ float g_k[(size_t)TROWS * DIMC];
__device__ float g_v[(size_t)TROWS * DIMC];
__device__ float g_o[(size_t)TROWS * DIMC];

// =================== helpers ================================================
__device__ __forceinline__ uint32_t smem_u32(const void* p) {
    uint32_t a;
    asm("{ .reg .u64 t; cvta.to.shared.u64 t, %1; cvt.u32.u64 %0, t; }"
        : "=r"(a) : "l"(p));
    return a;
}

#define CP_ASYNC16(dst, src) \
    asm volatile("cp.async.cg.shared.global [%0], [%1], 16;" \
                 :: "r"(dst), "l"(src) : "memory")
#define CP_COMMIT() asm volatile("cp.async.commit_group;" ::: "memory")
#define CP_WAIT(n)  asm volatile("cp.async.wait_group %0;" :: "n"(n) : "memory")

__device__ __forceinline__ uint32_t f2tf32(float x) {
    uint32_t u;
    asm("cvt.rna.tf32.f32 %0, %1;" : "=r"(u) : "f"(x));
    return u;
}

__device__ __forceinline__ void mma_tf32(float* c, const uint32_t* a,
                                         const uint32_t* b) {
    asm volatile(
        "mma.sync.aligned.m16n8k8.row.col.f32.tf32.tf32.f32 "
        "{%0,%1,%2,%3}, {%4,%5,%6,%7}, {%8,%9}, {%0,%1,%2,%3};"
        : "+f"(c[0]), "+f"(c[1]), "+f"(c[2]), "+f"(c[3])
        : "r"(a[0]), "r"(a[1]), "r"(a[2]), "r"(a[3]),
          "r"(b[0]), "r"(b[1]));
}

// =================== mma.sync TF32 GEMM =====================================
// C[M,1024] = A[M,1024] @ W[1024,1024]^T + bias.  A,W row-major K-contiguous.
// Block tile 128x128, BK=32, 4-stage cp.async pipeline, 8 warps (32x64 each).
// SMEM tile layout: [row][k] with 16B-group XOR swizzle: group g at
// phys group (g ^ (row & 7)) -> conflict-free stores and fragment loads.
#define GSTAGES     4
#define KT          32
#define KITERS      (DIMC / KT)              // 32
#define TILE_BYTES  16384                    // 128 rows x 32 floats
#define STAGE_BYTES (2 * TILE_BYTES)         // A + B
#define DSMEM_BYTES (GSTAGES * STAGE_BYTES)  // 128 KB

__global__ __launch_bounds__(256, 1)
void gemm_tc_kernel(const float* __restrict__ A,
                    const float* __restrict__ W,
                    const float* __restrict__ bias,
                    float* __restrict__ C)
{
    extern __shared__ char dsm[];
    float* sf = (float*)dsm;

    const int tid  = threadIdx.x;
    const int wid  = tid >> 5;
    const int lane = tid & 31;
    const int q    = lane >> 2;   // 0..7
    const int r    = lane & 3;    // 0..3
    const int wm   = wid & 3;     // warp m block (32 rows)
    const int wn   = wid >> 2;    // warp n block (64 cols)
    const int bm   = blockIdx.y * 128;
    const int bn   = blockIdx.x * 128;

    const uint32_t sbase = smem_u32(dsm);

    float acc[2][8][4];
#pragma unroll
    for (int f = 0; f < 2; ++f)
#pragma unroll
        for (int j = 0; j < 8; ++j)
#pragma unroll
            for (int c = 0; c < 4; ++c) acc[f][j][c] = 0.f;

    // stage loader: A tile 128x32 + B tile 128x32, swizzled float4 stores
    auto issue_stage = [&](int kt_idx, int buf) {
        const int k0 = kt_idx * KT;
        const uint32_t ab = sbase + buf * STAGE_BYTES;
        const uint32_t bb = ab + TILE_BYTES;
#pragma unroll
        for (int it = 0; it < 4; ++it) {
            const int e   = tid + it * 256;    // 0..1023
            const int row = e >> 3;
            const int g   = e & 7;
            const uint32_t off = (uint32_t)(row * 128 + ((g ^ (row & 7)) << 4));
            CP_ASYNC16(ab + off, &A[(size_t)(bm + row) * DIMC + k0 + g * 4]);
            CP_ASYNC16(bb + off, &W[(size_t)(bn + row) * DIMC + k0 + g * 4]);
        }
        CP_COMMIT();
    };

    issue_stage(0, 0);
    issue_stage(1, 1);
    issue_stage(2, 2);

    for (int kt = 0; kt < KITERS; ++kt) {
        if (kt < KITERS - 2) { CP_WAIT(2); } else { CP_WAIT(0); }
        __syncthreads();
        if (kt + 3 < KITERS) issue_stage(kt + 3, (kt + 3) & (GSTAGES - 1));

        const int buf = kt & (GSTAGES - 1);
        const float* sA = sf + (size_t)buf * (STAGE_BYTES / 4);
        const float* sB = sA + (TILE_BYTES / 4);

#pragma unroll
        for (int ks = 0; ks < 4; ++ks) {
            const int g0 = ks * 2;          // k-group of a0/b0
            const int g1 = g0 + 1;          // k-group of a2/b1 (col+4)
            const int sw0 = (g0 ^ q) * 4 + r;
            const int sw1 = (g1 ^ q) * 4 + r;

            uint32_t a[2][4];
#pragma unroll
            for (int f = 0; f < 2; ++f) {
                const int row0 = wm * 32 + f * 16 + q;     // row&7 == q
                const int row1 = row0 + 8;
                a[f][0] = f2tf32(sA[row0 * 32 + sw0]);
                a[f][1] = f2tf32(sA[row1 * 32 + sw0]);
                a[f][2] = f2tf32(sA[row0 * 32 + sw1]);
                a[f][3] = f2tf32(sA[row1 * 32 + sw1]);
            }
            uint32_t b[8][2];
#pragma unroll
            for (int j = 0; j < 8; ++j) {
                const int n0 = wn * 64 + j * 8 + q;        // n&7 == q
                b[j][0] = f2tf32(sB[n0 * 32 + sw0]);
                b[j][1] = f2tf32(sB[n0 * 32 + sw1]);
            }
#pragma unroll
            for (int f = 0; f < 2; ++f)
#pragma unroll
                for (int j = 0; j < 8; ++j)
                    mma_tf32(acc[f][j], a[f], b[j]);
        }
    }

    // epilogue: add bias, store (float2 per fragment row)
#pragma unroll
    for (int f = 0; f < 2; ++f) {
        const int row0 = bm + wm * 32 + f * 16 + q;
#pragma unroll
        for (int j = 0; j < 8; ++j) {
            const int col = bn + wn * 64 + j * 8 + r * 2;
            const float b0 = __ldg(&bias[col]);
            const float b1 = __ldg(&bias[col + 1]);
            float2 v0 = make_float2(acc[f][j][0] + b0, acc[f][j][1] + b1);
            float2 v1 = make_float2(acc[f][j][2] + b0, acc[f][j][3] + b1);
            *(float2*)&C[(size_t)row0 * DIMC + col]       = v0;
            *(float2*)&C[(size_t)(row0 + 8) * DIMC + col] = v1;
        }
    }
}

// ---------------- fused RMSNorm + RoPE (in place, one block per row) -------
__global__ __launch_bounds__(256)
void rmsnorm_rope_kernel(float* __restrict__ hk,
                         const float* __restrict__ w,
                         const float* __restrict__ fcos,
                         const float* __restrict__ fsin)
{
    const int t   = blockIdx.x;
    const int tid = threadIdx.x;
    const int col = tid * 4;

    float4 v = *(float4*)&hk[(size_t)t * DIMC + col];
    float local = v.x * v.x + v.y * v.y + v.z * v.z + v.w * v.w;

#pragma unroll
    for (int o = 16; o > 0; o >>= 1)
        local += __shfl_xor_sync(0xffffffffu, local, o);

    __shared__ float red[8];
    if ((tid & 31) == 0) red[tid >> 5] = local;
    __syncthreads();

    float tot = red[0] + red[1] + red[2] + red[3] +
                red[4] + red[5] + red[6] + red[7];
    const float scale = rsqrtf(tot * (1.0f / 1024.0f) + 1e-6f);

    float h0 = v.x * scale * w[col + 0];
    float h1 = v.y * scale * w[col + 1];
    float h2 = v.z * scale * w[col + 2];
    float h3 = v.w * scale * w[col + 3];

    const int dd0 = ((col & 63) >> 1);
    const int dd1 = dd0 + 1;
    const float c0 = fcos[(size_t)t * 32 + dd0];
    const float s0 = fsin[(size_t)t * 32 + dd0];
    const float c1 = fcos[(size_t)t * 32 + dd1];
    const float s1 = fsin[(size_t)t * 32 + dd1];

    float4 outv;
    outv.x = h0 * c0 - h1 * s0;
    outv.y = h0 * s0 + h1 * c0;
    outv.z = h2 * c1 - h3 * s1;
    outv.w = h2 * s1 + h3 * c1;
    *(float4*)&hk[(size_t)t * DIMC + col] = outv;
}

// ---------------- windowed frame attention ---------------------------------
__global__ __launch_bounds__(128)
void attn_kernel(const float* __restrict__ q,
                 const float* __restrict__ k,
                 const float* __restrict__ v,
                 float* __restrict__ o)
{
    const int si  = blockIdx.x;
    const int h   = blockIdx.y;
    const int tid = threadIdx.x;

    __shared__ float sq[16][64];
    __shared__ float sk[16][64];
    __shared__ float sv[16][64];
    __shared__ float sS[16][17];

#pragma unroll
    for (int e = tid; e < 256; e += 128) {
        const int frame = e >> 4;
        const int d4    = (e & 15) * 4;
        const size_t base = ((size_t)(frame * SQ + si)) * DIMC + h * HDC + d4;
        *(float4*)&sq[frame][d4] = *(const float4*)&q[base];
        *(float4*)&sk[frame][d4] = *(const float4*)&k[base];
        *(float4*)&sv[frame][d4] = *(const float4*)&v[base];
    }
    __syncthreads();

#pragma unroll
    for (int p = tid; p < 256; p += 128) {
        const int i = p >> 4;
        const int j = p & 15;
        float s;
        if (j <= i && (i - j) < WINDOW) {
            float accd = 0.f;
#pragma unroll
            for (int d = 0; d < 64; ++d) accd += sq[i][d] * sk[j][d];
            s = accd * 0.125f;
        } else {
            s = -1e30f;
        }
        sS[i][j] = s;
    }
    __syncthreads();

    if (tid < 16) {
        const int i = tid;
        float m = -1e30f;
#pragma unroll
        for (int j = 0; j < 16; ++j) m = fmaxf(m, sS[i][j]);
        float e[16];
        float sum = 0.f;
#pragma unroll
        for (int j = 0; j < 16; ++j) { e[j] = expf(sS[i][j] - m); sum += e[j]; }
        const float inv = 1.f / sum;
#pragma unroll
        for (int j = 0; j < 16; ++j) sS[i][j] = e[j] * inv;
    }
    __syncthreads();

#pragma unroll
    for (int e2 = tid; e2 < 1024; e2 += 128) {
        const int i = e2 >> 6;
        const int d = e2 & 63;
        float accd = 0.f;
#pragma unroll
        for (int j = 0; j < 16; ++j) accd += sS[i][j] * sv[j][d];
        o[((size_t)(i * SQ + si)) * DIMC + h * HDC + d] = accd;
    }
}

// ---------------- launch ----------------------------------------------------
extern "C" void kernel_launch(void* const* d_in, const int* in_sizes, int n_in,
                              void* d_out, int out_size)
{
    const float* x   = (const float*)d_in[0];
    const float* fc  = (const float*)d_in[1];
    const float* fs  = (const float*)d_in[2];
    const float* q_w = (const float*)d_in[3];
    const float* q_b = (const float*)d_in[4];
    const float* k_w = (const float*)d_in[5];
    const float* k_b = (const float*)d_in[6];
    const float* v_w = (const float*)d_in[7];
    const float* v_b = (const float*)d_in[8];
    const float* o_w = (const float*)d_in[9];
    const float* o_b = (const float*)d_in[10];
    const float* nqw = (const float*)d_in[11];
    const float* nkw = (const float*)d_in[12];
    float* out = (float*)d_out;

    float *gq, *gk, *gv, *go;
    cudaGetSymbolAddress((void**)&gq, g_q);
    cudaGetSymbolAddress((void**)&gk, g_k);
    cudaGetSymbolAddress((void**)&gv, g_v);
    cudaGetSymbolAddress((void**)&go, g_o);

    cudaFuncSetAttribute(gemm_tc_kernel,
                         cudaFuncAttributeMaxDynamicSharedMemorySize, DSMEM_BYTES);

    const dim3 gemm_grid(DIMC / 128, TROWS / 128);   // (8, 184)

    gemm_tc_kernel<<<gemm_grid, 256, DSMEM_BYTES>>>(x, q_w, q_b, gq);
    gemm_tc_kernel<<<gemm_grid, 256, DSMEM_BYTES>>>(x, k_w, k_b, gk);
    gemm_tc_kernel<<<gemm_grid, 256, DSMEM_BYTES>>>(x, v_w, v_b, gv);

    rmsnorm_rope_kernel<<<TROWS, 256>>>(gq, nqw, fc, fs);
    rmsnorm_rope_kernel<<<TROWS, 256>>>(gk, nkw, fc, fs);

    attn_kernel<<<dim3(SQ, NHC), 128>>>(gq, gk, gv, go);

    gemm_tc_kernel<<<gemm_grid, 256, DSMEM_BYTES>>>(go, o_w, o_b, out);
}